// round 3
// baseline (speedup 1.0000x reference)
#include <cuda_runtime.h>
#include <cstdint>
#include <math.h>

#define BB 8
#define NH 778
#define NO 50000
#define G 8
#define NGROUPS 98          // ceil(778/8)
#define NTHREADS 256

#define CONTACT2 (0.025f * 0.025f)

// Output layout (flattened tuple, float32):
// [0] missed_loss, [1] penetr_loss, [2..) results_close[B,NH,3],
// then minho[B,NH], max_penetr_depth, mean_penetr_depth
#define OFF_CLOSE 2
#define OFF_MINHO (2 + BB * NH * 3)
#define OFF_MAXD  (OFF_MINHO + BB * NH)
#define OFF_MEAND (OFF_MAXD + 1)

typedef unsigned long long ull;

// ---------- f32x2 packed helpers ----------
__device__ __forceinline__ ull pack2(float lo, float hi) {
    ull r; asm("mov.b64 %0, {%1, %2};" : "=l"(r) : "f"(lo), "f"(hi)); return r;
}
__device__ __forceinline__ void unpack2(ull v, float& lo, float& hi) {
    asm("mov.b64 {%0, %1}, %2;" : "=f"(lo), "=f"(hi) : "l"(v));
}
__device__ __forceinline__ ull fma2(ull a, ull b, ull c) {
    ull d; asm("fma.rn.f32x2 %0, %1, %2, %3;" : "=l"(d) : "l"(a), "l"(b), "l"(c)); return d;
}
__device__ __forceinline__ ull mul2(ull a, ull b) {
    ull d; asm("mul.rn.f32x2 %0, %1, %2;" : "=l"(d) : "l"(a), "l"(b)); return d;
}
__device__ __forceinline__ ull add2(ull a, ull b) {
    ull d; asm("add.rn.f32x2 %0, %1, %2;" : "=l"(d) : "l"(a), "l"(b)); return d;
}

// ---------- Kernel 1: per-hand-vertex nearest object point ----------
// Grid (NGROUPS, B). Block owns G hand verts, scans NO points as NO/2 packed
// pairs. Selection metric: dist2 = (rx + ry) - 2*zz  (reference formula).
__global__ void __launch_bounds__(NTHREADS)
nn_kernel(const float* __restrict__ hand, const float* __restrict__ obj,
          float* __restrict__ out)
{
    const int b     = blockIdx.y;
    const int vbase = blockIdx.x * G;
    const int tid   = threadIdx.x;
    const int lane  = tid & 31;
    const int warp  = tid >> 5;

    __shared__ float sh[G * 3];
    __shared__ float swb[NTHREADS / 32][G];
    __shared__ int   swi[NTHREADS / 32][G];

    if (tid < G * 3) {
        int v = vbase + tid / 3;
        if (v >= NH) v = NH - 1;                   // pad with a valid vertex
        sh[tid] = hand[(b * NH + v) * 3 + (tid % 3)];
    }
    __syncthreads();

    ull HX[G], HY[G], HZ[G], RX2[G];
#pragma unroll
    for (int v = 0; v < G; v++) {
        float x = sh[3 * v], y = sh[3 * v + 1], z = sh[3 * v + 2];
        HX[v] = pack2(x, x); HY[v] = pack2(y, y); HZ[v] = pack2(z, z);
        float rx = x * x + y * y + z * z;
        RX2[v] = pack2(rx, rx);
    }
    const ull NEG2 = pack2(-2.0f, -2.0f);

    float best[G];
    int   bidx[G];
#pragma unroll
    for (int v = 0; v < G; v++) { best[v] = 3.0e38f; bidx[v] = 0; }

    const float2* ob2 = reinterpret_cast<const float2*>(obj + (size_t)b * NO * 3);

    for (int p = tid; p < NO / 2; p += NTHREADS) {
        float2 a = __ldg(ob2 + 3 * p);          // (x0, y0)
        float2 c = __ldg(ob2 + 3 * p + 1);      // (z0, x1)
        float2 e = __ldg(ob2 + 3 * p + 2);      // (y1, z1)
        ull X2 = pack2(a.x, c.y);
        ull Y2 = pack2(a.y, e.x);
        ull Z2 = pack2(c.x, e.y);
        ull RY2 = fma2(X2, X2, fma2(Y2, Y2, mul2(Z2, Z2)));
        const int i0 = 2 * p;
#pragma unroll
        for (int v = 0; v < G; v++) {
            ull ZZ = fma2(HX[v], X2, fma2(HY[v], Y2, mul2(HZ[v], Z2)));
            ull D  = fma2(NEG2, ZZ, add2(RX2[v], RY2));   // (rx+ry) - 2*zz
            float d0, d1; unpack2(D, d0, d1);
            float m = fminf(d0, d1);
            if (m < best[v]) { best[v] = m; bidx[v] = i0 + (d1 < d0 ? 1 : 0); }
        }
    }

    // warp-level argmin merge
#pragma unroll
    for (int v = 0; v < G; v++) {
#pragma unroll
        for (int off = 16; off > 0; off >>= 1) {
            float ob = __shfl_down_sync(0xffffffffu, best[v], off);
            int   oi = __shfl_down_sync(0xffffffffu, bidx[v], off);
            if (ob < best[v]) { best[v] = ob; bidx[v] = oi; }
        }
    }
    if (lane == 0) {
#pragma unroll
        for (int v = 0; v < G; v++) { swb[warp][v] = best[v]; swi[warp][v] = bidx[v]; }
    }
    __syncthreads();

    if (tid < G) {
        const int v = tid;
        float bb = swb[0][v];
        int   bi = swi[0][v];
#pragma unroll
        for (int w = 1; w < NTHREADS / 32; w++)
            if (swb[w][v] < bb) { bb = swb[w][v]; bi = swi[w][v]; }
        const int vert = vbase + v;
        if (vert < NH) {
            const float* o = obj + ((size_t)b * NO + bi) * 3;
            float ox = o[0], oy = o[1], oz = o[2];
            float hx = sh[3 * v], hy = sh[3 * v + 1], hz = sh[3 * v + 2];
            // reference-form minho: (rx + ry) - 2*zz
            float rx = hx * hx + hy * hy + hz * hz;
            float ry = ox * ox + oy * oy + oz * oz;
            float zz = hx * ox + hy * oy + hz * oz;
            float minho = fmaf(-2.0f, zz, rx + ry);
            const int gi = b * NH + vert;
            out[OFF_MINHO + gi]         = minho;
            out[OFF_CLOSE + gi * 3 + 0] = ox;
            out[OFF_CLOSE + gi * 3 + 1] = oy;
            out[OFF_CLOSE + gi * 3 + 2] = oz;
        }
    }
}

// ---------- Kernel 2: losses + depth stats ----------
__global__ void __launch_bounds__(1024)
finalize_kernel(const float* __restrict__ hand, const void* __restrict__ ext_raw,
                int ext_elems, float* __restrict__ out)
{
    const float* minho = out + OFF_MINHO;
    const float* close = out + OFF_CLOSE;

    __shared__ float acc[4];   // sum_missed, cnt_missed, sum_pen, cnt_pen
    __shared__ float bsum[BB];
    __shared__ int   bmax[BB];
    __shared__ int   is_int32; // exterior dtype flag

    const int tid = threadIdx.x;
    if (tid < 4) acc[tid] = 0.0f;
    if (tid < BB) { bsum[tid] = 0.0f; bmax[tid] = 0; }
    if (tid == 0) is_int32 = 1;
    __syncthreads();

    // dtype detection. If the harness reports byte-count == B*NH the buffer is
    // uint8. If it reports element-count == B*NH it could be either; probe:
    // reinterpret the first B*NH bytes as int32 — random 0/1 bytes packed 4 to
    // a word are never all in {0,1} as int32s, while int32 bools always are.
    {
        int by_size_u8 = 0;
        // If size semantics are bytes for a bool tensor, either way ext_elems
        // == B*NH here; rely on the content probe.
        const int* ei = (const int*)ext_raw;
        int bad = by_size_u8;
        for (int i = tid; i < (BB * NH) / 4; i += blockDim.x) {
            unsigned v = (unsigned)ei[i];
            if (v > 1u) bad = 1;
        }
        if (__syncthreads_or(bad)) { if (tid == 0) is_int32 = 0; }
        __syncthreads();
    }
    const int int32mode = is_int32;
    const int* ei = (const int*)ext_raw;
    const unsigned char* eb = (const unsigned char*)ext_raw;

    float lsm = 0.0f, lcm = 0.0f, lsp = 0.0f, lcp = 0.0f;
    for (int i = tid; i < BB * NH; i += blockDim.x) {
        bool e = int32mode ? (ei[i] != 0) : (eb[i] != 0);
        // diff-form contact value / anchor (reference: closest - hand)
        float dx = close[i * 3 + 0] - hand[i * 3 + 0];
        float dy = close[i * 3 + 1] - hand[i * 3 + 1];
        float dz = close[i * 3 + 2] - hand[i * 3 + 2];
        float cv = dx * dx + dy * dy + dz * dz;
        float anchor = sqrtf(cv);
        if (e && (minho[i] < CONTACT2)) { lsm += cv; lcm += 1.0f; }
        if (!e) {
            lsp += 0.025f * tanhf(anchor * 40.0f);
            lcp += 1.0f;
            int b = i / NH;
            atomicAdd(&bsum[b], anchor);
            atomicMax(&bmax[b], __float_as_int(anchor));
        }
    }
#pragma unroll
    for (int off = 16; off > 0; off >>= 1) {
        lsm += __shfl_down_sync(0xffffffffu, lsm, off);
        lcm += __shfl_down_sync(0xffffffffu, lcm, off);
        lsp += __shfl_down_sync(0xffffffffu, lsp, off);
        lcp += __shfl_down_sync(0xffffffffu, lcp, off);
    }
    if ((tid & 31) == 0) {
        atomicAdd(&acc[0], lsm);
        atomicAdd(&acc[1], lcm);
        atomicAdd(&acc[2], lsp);
        atomicAdd(&acc[3], lcp);
    }
    __syncthreads();

    if (tid == 0) {
        float missed = (acc[1] > 0.0f) ? acc[0] / fmaxf(acc[1], 1.0f) : 0.0f;
        float penetr = (acc[3] > 0.0f) ? acc[2] / fmaxf(acc[3], 1.0f) : 0.0f;
        float mx = 0.0f, mn = 0.0f;
#pragma unroll
        for (int b = 0; b < BB; b++) {
            mx += __int_as_float(bmax[b]);
            mn += bsum[b] * (1.0f / (float)NH);
        }
        out[0]         = missed;
        out[1]         = penetr;
        out[OFF_MAXD]  = mx * (1.0f / (float)BB);
        out[OFF_MEAND] = mn * (1.0f / (float)BB);
    }
}

extern "C" void kernel_launch(void* const* d_in, const int* in_sizes, int n_in,
                              void* d_out, int out_size)
{
    const float* hand = (const float*)d_in[0];   // [8,778,3]
    const float* obj  = (const float*)d_in[1];   // [8,50000,3]
    const void*  ext  = d_in[2];                 // [8,778] bool or int32
    float* out = (float*)d_out;

    dim3 grid(NGROUPS, BB);
    nn_kernel<<<grid, NTHREADS>>>(hand, obj, out);
    finalize_kernel<<<1, 1024>>>(hand, ext, in_sizes[2], out);
}

// round 4
// speedup vs baseline: 1.3896x; 1.3896x over previous
#include <cuda_runtime.h>
#include <cstdint>
#include <math.h>

#define BB 8
#define NH 778
#define NO 50000
#define G 8
#define NGROUPS 98          // ceil(778/8)
#define NTHREADS 256

#define CONTACT2 (0.025f * 0.025f)

// Output layout (flattened tuple, float32):
// [0] missed_loss, [1] penetr_loss, [2..) results_close[B,NH,3],
// then minho[B,NH], max_penetr_depth, mean_penetr_depth
#define OFF_CLOSE 2
#define OFF_MINHO (2 + BB * NH * 3)
#define OFF_MAXD  (OFF_MINHO + BB * NH)
#define OFF_MEAND (OFF_MAXD + 1)

typedef unsigned long long ull;

// ---------- device scratch (no allocation allowed) ----------
__device__ float g_acc[4];     // missed_sum, missed_cnt, pen_sum, pen_cnt
__device__ float g_bsum[BB];   // per-batch sum of masked anchor dists
__device__ int   g_bmax[BB];   // per-batch max anchor (float bits, >= 0)
__device__ int   g_extint;     // 1 if exterior buffer is int32, 0 if uint8

// ---------- f32x2 packed helpers ----------
__device__ __forceinline__ ull pack2(float lo, float hi) {
    ull r; asm("mov.b64 %0, {%1, %2};" : "=l"(r) : "f"(lo), "f"(hi)); return r;
}
__device__ __forceinline__ void unpack2(ull v, float& lo, float& hi) {
    asm("mov.b64 {%0, %1}, %2;" : "=f"(lo), "=f"(hi) : "l"(v));
}
__device__ __forceinline__ ull fma2(ull a, ull b, ull c) {
    ull d; asm("fma.rn.f32x2 %0, %1, %2, %3;" : "=l"(d) : "l"(a), "l"(b), "l"(c)); return d;
}
__device__ __forceinline__ ull mul2(ull a, ull b) {
    ull d; asm("mul.rn.f32x2 %0, %1, %2;" : "=l"(d) : "l"(a), "l"(b)); return d;
}
__device__ __forceinline__ ull add2(ull a, ull b) {
    ull d; asm("add.rn.f32x2 %0, %1, %2;" : "=l"(d) : "l"(a), "l"(b)); return d;
}

// ---------- Kernel 0: zero accumulators + exterior dtype probe ----------
__global__ void __launch_bounds__(256)
init_kernel(const void* __restrict__ ext_raw)
{
    const int tid = threadIdx.x;
    if (tid < 4) g_acc[tid] = 0.0f;
    if (tid >= 4 && tid < 4 + BB) g_bsum[tid - 4] = 0.0f;
    if (tid >= 16 && tid < 16 + BB) g_bmax[tid - 16] = 0;

    // Probe: reinterpret first B*NH bytes as int32s. Random 0/1 bytes packed
    // 4-per-word are (essentially) never all in {0,1} as int32; int32 bool
    // values always are.
    const int* ei = (const int*)ext_raw;
    int bad = 0;
    for (int i = tid; i < (BB * NH) / 4; i += 256) {
        unsigned v = (unsigned)ei[i];
        if (v > 1u) bad = 1;
    }
    int any_bad = __syncthreads_or(bad);
    if (tid == 0) g_extint = any_bad ? 0 : 1;
}

// ---------- Kernel 1: nearest object point + fused stats ----------
// Grid (NGROUPS, B). Block owns G hand verts, scans NO points as NO/2 packed
// pairs. Selection metric bit-path: fma(-2, zz, rx+ry)  (matches passing R3).
__global__ void __launch_bounds__(NTHREADS)
nn_kernel(const float* __restrict__ hand, const float* __restrict__ obj,
          const void* __restrict__ ext_raw, float* __restrict__ out)
{
    const int b     = blockIdx.y;
    const int vbase = blockIdx.x * G;
    const int tid   = threadIdx.x;
    const int lane  = tid & 31;
    const int warp  = tid >> 5;

    __shared__ float sh[G * 3];
    __shared__ float swb[NTHREADS / 32][G];
    __shared__ int   swi[NTHREADS / 32][G];

    if (tid < G * 3) {
        int v = vbase + tid / 3;
        if (v >= NH) v = NH - 1;                   // pad with a valid vertex
        sh[tid] = hand[(b * NH + v) * 3 + (tid % 3)];
    }
    __syncthreads();

    ull HX[G], HY[G], HZ[G], RX2[G];
#pragma unroll
    for (int v = 0; v < G; v++) {
        float x = sh[3 * v], y = sh[3 * v + 1], z = sh[3 * v + 2];
        HX[v] = pack2(x, x); HY[v] = pack2(y, y); HZ[v] = pack2(z, z);
        float rx = x * x + y * y + z * z;
        RX2[v] = pack2(rx, rx);
    }
    const ull NEG2 = pack2(-2.0f, -2.0f);

    float best[G];
    int   bidx[G];                                 // PAIR index (point = 2p or 2p+1)
#pragma unroll
    for (int v = 0; v < G; v++) { best[v] = 3.0e38f; bidx[v] = 0; }

    const float2* ob2 = reinterpret_cast<const float2*>(obj + (size_t)b * NO * 3);

    for (int p = tid; p < NO / 2; p += NTHREADS) {
        float2 a = __ldg(ob2 + 3 * p);          // (x0, y0)
        float2 c = __ldg(ob2 + 3 * p + 1);      // (z0, x1)
        float2 e = __ldg(ob2 + 3 * p + 2);      // (y1, z1)
        ull X2 = pack2(a.x, c.y);
        ull Y2 = pack2(a.y, e.x);
        ull Z2 = pack2(c.x, e.y);
        ull RY2 = fma2(X2, X2, fma2(Y2, Y2, mul2(Z2, Z2)));
#pragma unroll
        for (int v = 0; v < G; v++) {
            ull ZZ = fma2(HX[v], X2, fma2(HY[v], Y2, mul2(HZ[v], Z2)));
            ull D  = fma2(NEG2, ZZ, add2(RX2[v], RY2));   // (rx+ry) - 2*zz
            float d0, d1; unpack2(D, d0, d1);
            float m = fminf(d0, d1);
            if (m < best[v]) { best[v] = m; bidx[v] = p; }
        }
    }

    // warp-level argmin merge
#pragma unroll
    for (int v = 0; v < G; v++) {
#pragma unroll
        for (int off = 16; off > 0; off >>= 1) {
            float ob = __shfl_down_sync(0xffffffffu, best[v], off);
            int   oi = __shfl_down_sync(0xffffffffu, bidx[v], off);
            if (ob < best[v]) { best[v] = ob; bidx[v] = oi; }
        }
    }
    if (lane == 0) {
#pragma unroll
        for (int v = 0; v < G; v++) { swb[warp][v] = best[v]; swi[warp][v] = bidx[v]; }
    }
    __syncthreads();

    if (tid < G) {
        const int v = tid;
        float bb = swb[0][v];
        int   bp = swi[0][v];
#pragma unroll
        for (int w = 1; w < NTHREADS / 32; w++)
            if (swb[w][v] < bb) { bb = swb[w][v]; bp = swi[w][v]; }
        const int vert = vbase + v;
        if (vert < NH) {
            float hx = sh[3 * v], hy = sh[3 * v + 1], hz = sh[3 * v + 2];
            float rx = hx * hx + hy * hy + hz * hz;

            // resolve which of the two points in winning pair bp is closest,
            // using the exact same fp path as the inner loop.
            const float* o0 = obj + ((size_t)b * NO + 2 * bp) * 3;
            float x0 = o0[0], y0 = o0[1], z0 = o0[2];
            float x1 = o0[3], y1 = o0[4], z1 = o0[5];
            float ry0 = x0 * x0 + y0 * y0 + z0 * z0;
            float ry1 = x1 * x1 + y1 * y1 + z1 * z1;
            float zz0 = hx * x0 + hy * y0 + hz * z0;
            float zz1 = hx * x1 + hy * y1 + hz * z1;
            float dd0 = fmaf(-2.0f, zz0, rx + ry0);
            float dd1 = fmaf(-2.0f, zz1, rx + ry1);
            bool second = (dd1 < dd0);
            float ox = second ? x1 : x0;
            float oy = second ? y1 : y0;
            float oz = second ? z1 : z0;
            float minho = second ? dd1 : dd0;

            const int gi = b * NH + vert;
            out[OFF_MINHO + gi]         = minho;
            out[OFF_CLOSE + gi * 3 + 0] = ox;
            out[OFF_CLOSE + gi * 3 + 1] = oy;
            out[OFF_CLOSE + gi * 3 + 2] = oz;

            // ---- fused stats (reference: diff = closest - hand) ----
            bool e;
            if (g_extint) e = (((const int*)ext_raw)[gi] != 0);
            else          e = (((const unsigned char*)ext_raw)[gi] != 0);

            float dx = ox - hx, dy = oy - hy, dz = oz - hz;
            float cv = dx * dx + dy * dy + dz * dz;
            float anchor = sqrtf(cv);
            if (e && (minho < CONTACT2)) {
                atomicAdd(&g_acc[0], cv);
                atomicAdd(&g_acc[1], 1.0f);
            }
            if (!e) {
                atomicAdd(&g_acc[2], 0.025f * tanhf(anchor * 40.0f));
                atomicAdd(&g_acc[3], 1.0f);
                atomicAdd(&g_bsum[b], anchor);
                atomicMax(&g_bmax[b], __float_as_int(anchor));
            }
        }
    }
}

// ---------- Kernel 2: emit scalars ----------
__global__ void __launch_bounds__(32)
final_kernel(float* __restrict__ out)
{
    if (threadIdx.x == 0) {
        float missed = (g_acc[1] > 0.0f) ? g_acc[0] / fmaxf(g_acc[1], 1.0f) : 0.0f;
        float penetr = (g_acc[3] > 0.0f) ? g_acc[2] / fmaxf(g_acc[3], 1.0f) : 0.0f;
        float mx = 0.0f, mn = 0.0f;
#pragma unroll
        for (int b = 0; b < BB; b++) {
            mx += __int_as_float(g_bmax[b]);
            mn += g_bsum[b] * (1.0f / (float)NH);
        }
        out[0]         = missed;
        out[1]         = penetr;
        out[OFF_MAXD]  = mx * (1.0f / (float)BB);
        out[OFF_MEAND] = mn * (1.0f / (float)BB);
    }
}

extern "C" void kernel_launch(void* const* d_in, const int* in_sizes, int n_in,
                              void* d_out, int out_size)
{
    const float* hand = (const float*)d_in[0];   // [8,778,3]
    const float* obj  = (const float*)d_in[1];   // [8,50000,3]
    const void*  ext  = d_in[2];                 // [8,778] bool or int32
    float* out = (float*)d_out;

    init_kernel<<<1, 256>>>(ext);
    dim3 grid(NGROUPS, BB);
    nn_kernel<<<grid, NTHREADS>>>(hand, obj, ext, out);
    final_kernel<<<1, 32>>>(out);
}

// round 5
// speedup vs baseline: 1.4344x; 1.0322x over previous
#include <cuda_runtime.h>
#include <cstdint>
#include <math.h>

#define BB 8
#define NH 778
#define NO 50000
#define G 8
#define NGROUPS 98          // ceil(778/8)
#define NTHREADS 256
#define NBLOCKS (NGROUPS * BB)

#define CONTACT2 (0.025f * 0.025f)

// Output layout (flattened tuple, float32):
// [0] missed_loss, [1] penetr_loss, [2..) results_close[B,NH,3],
// then minho[B,NH], max_penetr_depth, mean_penetr_depth
#define OFF_CLOSE 2
#define OFF_MINHO (2 + BB * NH * 3)
#define OFF_MAXD  (OFF_MINHO + BB * NH)
#define OFF_MEAND (OFF_MAXD + 1)

typedef unsigned long long ull;

// ---------- device scratch (zero-initialized at module load; the last
// finishing block resets everything to zero so each graph replay starts
// from clean state) ----------
__device__ float g_acc[4];     // missed_sum, missed_cnt, pen_sum, pen_cnt
__device__ float g_bsum[BB];   // per-batch sum of masked anchor dists
__device__ int   g_bmax[BB];   // per-batch max anchor (float bits, >= 0)
__device__ int   g_done;       // completed-block counter

// ---------- f32x2 packed helpers ----------
__device__ __forceinline__ ull pack2(float lo, float hi) {
    ull r; asm("mov.b64 %0, {%1, %2};" : "=l"(r) : "f"(lo), "f"(hi)); return r;
}
__device__ __forceinline__ void unpack2(ull v, float& lo, float& hi) {
    asm("mov.b64 {%0, %1}, %2;" : "=f"(lo), "=f"(hi) : "l"(v));
}
__device__ __forceinline__ ull fma2(ull a, ull b, ull c) {
    ull d; asm("fma.rn.f32x2 %0, %1, %2, %3;" : "=l"(d) : "l"(a), "l"(b), "l"(c)); return d;
}
__device__ __forceinline__ ull mul2(ull a, ull b) {
    ull d; asm("mul.rn.f32x2 %0, %1, %2;" : "=l"(d) : "l"(a), "l"(b)); return d;
}
__device__ __forceinline__ ull add2(ull a, ull b) {
    ull d; asm("add.rn.f32x2 %0, %1, %2;" : "=l"(d) : "l"(a), "l"(b)); return d;
}

// ---------- Single fused kernel ----------
// Grid (NGROUPS, B). Block owns G hand verts, scans NO points as NO/2 packed
// pairs. Selection metric bit-path identical to the 137us passing kernel.
__global__ void __launch_bounds__(NTHREADS)
nn_kernel(const float* __restrict__ hand, const float* __restrict__ obj,
          const void* __restrict__ ext_raw, float* __restrict__ out)
{
    const int b     = blockIdx.y;
    const int vbase = blockIdx.x * G;
    const int tid   = threadIdx.x;
    const int lane  = tid & 31;
    const int warp  = tid >> 5;

    __shared__ float sh[G * 3];
    __shared__ float swb[NTHREADS / 32][G];
    __shared__ int   swi[NTHREADS / 32][G];
    __shared__ int   s_extint;

    if (tid < G * 3) {
        int v = vbase + tid / 3;
        if (v >= NH) v = NH - 1;                   // pad with a valid vertex
        sh[tid] = hand[(b * NH + v) * 3 + (tid % 3)];
    }
    if (tid == 0) {
        // dtype probe: first 16 int32 words all in {0,1} <=> int32 bool array
        // (random packed 0/1 bytes fail with probability 1 - 8^-16).
        const int* ei = (const int*)ext_raw;
        int ok = 1;
#pragma unroll
        for (int i = 0; i < 16; i++) {
            unsigned v = (unsigned)ei[i];
            if (v > 1u) ok = 0;
        }
        s_extint = ok;
    }
    __syncthreads();

    ull HX[G], HY[G], HZ[G], RX2[G];
#pragma unroll
    for (int v = 0; v < G; v++) {
        float x = sh[3 * v], y = sh[3 * v + 1], z = sh[3 * v + 2];
        HX[v] = pack2(x, x); HY[v] = pack2(y, y); HZ[v] = pack2(z, z);
        float rx = x * x + y * y + z * z;
        RX2[v] = pack2(rx, rx);
    }
    const ull NEG2 = pack2(-2.0f, -2.0f);

    float best[G];
    int   bidx[G];                                 // PAIR index (point = 2p or 2p+1)
#pragma unroll
    for (int v = 0; v < G; v++) { best[v] = 3.0e38f; bidx[v] = 0; }

    const float2* ob2 = reinterpret_cast<const float2*>(obj + (size_t)b * NO * 3);

    for (int p = tid; p < NO / 2; p += NTHREADS) {
        float2 a = __ldg(ob2 + 3 * p);          // (x0, y0)
        float2 c = __ldg(ob2 + 3 * p + 1);      // (z0, x1)
        float2 e = __ldg(ob2 + 3 * p + 2);      // (y1, z1)
        ull X2 = pack2(a.x, c.y);
        ull Y2 = pack2(a.y, e.x);
        ull Z2 = pack2(c.x, e.y);
        ull RY2 = fma2(X2, X2, fma2(Y2, Y2, mul2(Z2, Z2)));
#pragma unroll
        for (int v = 0; v < G; v++) {
            ull ZZ = fma2(HX[v], X2, fma2(HY[v], Y2, mul2(HZ[v], Z2)));
            ull D  = fma2(NEG2, ZZ, add2(RX2[v], RY2));   // (rx+ry) - 2*zz
            float d0, d1; unpack2(D, d0, d1);
            float m = fminf(d0, d1);
            if (m < best[v]) { best[v] = m; bidx[v] = p; }
        }
    }

    // warp-level argmin merge
#pragma unroll
    for (int v = 0; v < G; v++) {
#pragma unroll
        for (int off = 16; off > 0; off >>= 1) {
            float ob = __shfl_down_sync(0xffffffffu, best[v], off);
            int   oi = __shfl_down_sync(0xffffffffu, bidx[v], off);
            if (ob < best[v]) { best[v] = ob; bidx[v] = oi; }
        }
    }
    if (lane == 0) {
#pragma unroll
        for (int v = 0; v < G; v++) { swb[warp][v] = best[v]; swi[warp][v] = bidx[v]; }
    }
    __syncthreads();

    if (tid < G) {
        const int v = tid;
        float bb = swb[0][v];
        int   bp = swi[0][v];
#pragma unroll
        for (int w = 1; w < NTHREADS / 32; w++)
            if (swb[w][v] < bb) { bb = swb[w][v]; bp = swi[w][v]; }
        const int vert = vbase + v;
        if (vert < NH) {
            float hx = sh[3 * v], hy = sh[3 * v + 1], hz = sh[3 * v + 2];
            float rx = hx * hx + hy * hy + hz * hz;

            // resolve which of the two points in winning pair bp is closest,
            // using the exact same fp path as the inner loop.
            const float* o0 = obj + ((size_t)b * NO + 2 * bp) * 3;
            float x0 = o0[0], y0 = o0[1], z0 = o0[2];
            float x1 = o0[3], y1 = o0[4], z1 = o0[5];
            float ry0 = x0 * x0 + y0 * y0 + z0 * z0;
            float ry1 = x1 * x1 + y1 * y1 + z1 * z1;
            float zz0 = hx * x0 + hy * y0 + hz * z0;
            float zz1 = hx * x1 + hy * y1 + hz * z1;
            float dd0 = fmaf(-2.0f, zz0, rx + ry0);
            float dd1 = fmaf(-2.0f, zz1, rx + ry1);
            bool second = (dd1 < dd0);
            float ox = second ? x1 : x0;
            float oy = second ? y1 : y0;
            float oz = second ? z1 : z0;
            float minho = second ? dd1 : dd0;

            const int gi = b * NH + vert;
            out[OFF_MINHO + gi]         = minho;
            out[OFF_CLOSE + gi * 3 + 0] = ox;
            out[OFF_CLOSE + gi * 3 + 1] = oy;
            out[OFF_CLOSE + gi * 3 + 2] = oz;

            // ---- fused stats (reference: diff = closest - hand) ----
            bool e;
            if (s_extint) e = (((const int*)ext_raw)[gi] != 0);
            else          e = (((const unsigned char*)ext_raw)[gi] != 0);

            float dx = ox - hx, dy = oy - hy, dz = oz - hz;
            float cv = dx * dx + dy * dy + dz * dz;
            float anchor = sqrtf(cv);
            if (e && (minho < CONTACT2)) {
                atomicAdd(&g_acc[0], cv);
                atomicAdd(&g_acc[1], 1.0f);
            }
            if (!e) {
                atomicAdd(&g_acc[2], 0.025f * tanhf(anchor * 40.0f));
                atomicAdd(&g_acc[3], 1.0f);
                atomicAdd(&g_bsum[b], anchor);
                atomicMax(&g_bmax[b], __float_as_int(anchor));
            }
        }
    }

    // ---- last-block-done: emit scalars and reset scratch ----
    __syncthreads();
    if (tid == 0) {
        __threadfence();
        int prev = atomicAdd(&g_done, 1);
        if (prev == NBLOCKS - 1) {
            __threadfence();
            float a0 = g_acc[0], a1 = g_acc[1], a2 = g_acc[2], a3 = g_acc[3];
            float missed = (a1 > 0.0f) ? a0 / fmaxf(a1, 1.0f) : 0.0f;
            float penetr = (a3 > 0.0f) ? a2 / fmaxf(a3, 1.0f) : 0.0f;
            float mx = 0.0f, mn = 0.0f;
#pragma unroll
            for (int bb2 = 0; bb2 < BB; bb2++) {
                mx += __int_as_float(g_bmax[bb2]);
                mn += g_bsum[bb2] * (1.0f / (float)NH);
            }
            out[0]         = missed;
            out[1]         = penetr;
            out[OFF_MAXD]  = mx * (1.0f / (float)BB);
            out[OFF_MEAND] = mn * (1.0f / (float)BB);
            // reset scratch for next replay
            g_acc[0] = 0.0f; g_acc[1] = 0.0f; g_acc[2] = 0.0f; g_acc[3] = 0.0f;
#pragma unroll
            for (int bb2 = 0; bb2 < BB; bb2++) { g_bsum[bb2] = 0.0f; g_bmax[bb2] = 0; }
            g_done = 0;
        }
    }
}

extern "C" void kernel_launch(void* const* d_in, const int* in_sizes, int n_in,
                              void* d_out, int out_size)
{
    const float* hand = (const float*)d_in[0];   // [8,778,3]
    const float* obj  = (const float*)d_in[1];   // [8,50000,3]
    const void*  ext  = d_in[2];                 // [8,778] bool or int32
    float* out = (float*)d_out;

    dim3 grid(NGROUPS, BB);
    nn_kernel<<<grid, NTHREADS>>>(hand, obj, ext, out);
}